// round 5
// baseline (speedup 1.0000x reference)
#include <cuda_runtime.h>
#include <math.h>
#include <stdint.h>

#define N_Y   100000
#define N_X   20000
#define KNN   16
#define NE    (N_X * KNN)      // 320000 edges
#define HID   256
#define CIN   64

#define SA_P 20     // A smem row pitch (words): ldmatrix conflict-free
#define PK   20     // B smem row pitch (words), [n][k] layout

// Scratch (device globals: allocation-free contract)
__device__ float    g_Ay[(size_t)N_Y * HID];
__device__ float    g_Bx[(size_t)N_X * HID];
// transposed + tf32-converted weights, [n][k] dense
__device__ uint32_t g_W1aT[256 * 192];
__device__ uint32_t g_W1bT[256 * 192];
__device__ uint32_t g_W2T[256 * 256];
__device__ uint32_t g_W3T[64 * 256];

__device__ __forceinline__ float gelu_f(float v) {
    return 0.5f * v * (1.0f + erff(v * 0.70710678118654752f));
}
__device__ __forceinline__ uint32_t f2tf32(float x) {
    uint32_t r;
    asm("cvt.rna.tf32.f32 %0, %1;" : "=r"(r) : "f"(x));
    return r;
}
__device__ __forceinline__ void mma_tf32(float* d, const uint32_t* a, const uint32_t* b) {
    asm volatile(
        "mma.sync.aligned.m16n8k8.row.col.f32.tf32.tf32.f32 "
        "{%0,%1,%2,%3}, {%4,%5,%6,%7}, {%8,%9}, {%0,%1,%2,%3};\n"
        : "+f"(d[0]), "+f"(d[1]), "+f"(d[2]), "+f"(d[3])
        : "r"(a[0]), "r"(a[1]), "r"(a[2]), "r"(a[3]), "r"(b[0]), "r"(b[1]));
}
__device__ __forceinline__ void ldsm_x4(uint32_t* r, uint32_t saddr) {
    asm volatile("ldmatrix.sync.aligned.m8n8.x4.shared.b16 {%0,%1,%2,%3}, [%4];"
                 : "=r"(r[0]), "=r"(r[1]), "=r"(r[2]), "=r"(r[3]) : "r"(saddr));
}
__device__ __forceinline__ uint32_t smem_u32(const void* p) {
    return (uint32_t)__cvta_generic_to_shared(p);
}
// per-lane ldmatrix byte offsets
__device__ __forceinline__ uint32_t a_lane_off(int lane) {
    return 4u * ((lane & 15) * SA_P + ((lane >> 4) << 2));
}
__device__ __forceinline__ uint32_t b_lane_off(int lane) {
    return 4u * (((lane & 7) + ((lane >> 4) << 3)) * PK + (((lane >> 3) & 1) << 2));
}

// ---------------------------------------------------------------------------
// Weight transpose + tf32 convert: src fp32 [K][N] -> dst u32 [N][K]
// ---------------------------------------------------------------------------
__device__ __forceinline__ uint32_t* sel_dst(int w) {
    return w == 0 ? g_W1aT : w == 1 ? g_W1bT : w == 2 ? g_W2T : g_W3T;
}
__global__ void transpose_cvt_kernel(const float* __restrict__ src, int K, int N, int w)
{
    __shared__ float t[32][33];
    uint32_t* dst = sel_dst(w);
    int k0 = blockIdx.y * 32, n0 = blockIdx.x * 32;
    int tx = threadIdx.x, ty = threadIdx.y;   // 32 x 8
#pragma unroll
    for (int i = 0; i < 32; i += 8)
        t[ty + i][tx] = src[(size_t)(k0 + ty + i) * N + n0 + tx];
    __syncthreads();
#pragma unroll
    for (int i = 0; i < 32; i += 8)
        dst[(size_t)(n0 + ty + i) * K + k0 + tx] = f2tf32(t[tx][ty + i]);
}

// ---------------------------------------------------------------------------
// Embed + GEMM1: dst = emb(pts) @ W (+bias).  BM=128, BN=256, K=192.
// ---------------------------------------------------------------------------
__global__ void __launch_bounds__(512) embed_mma_kernel(
    const float* __restrict__ pts,
    const float* __restrict__ bias,
    int which, int n)
{
    __shared__ uint32_t sA[128 * SA_P];
    __shared__ uint32_t sB[256 * PK];
    __shared__ float s_pts[128 * 3];
    __shared__ float s_freq[32];

    const uint32_t* WT = which ? g_W1bT : g_W1aT;
    float* dst = which ? g_Bx : g_Ay;
    const int tid  = threadIdx.x;
    const int row0 = blockIdx.x * 128;
    const int warp = tid >> 5, lane = tid & 31;
    const int wm = (warp & 3) * 32, wn = (warp >> 2) * 64;
    const int lr = lane >> 2, lc = lane & 3;
    const uint32_t sAu = smem_u32(sA) + a_lane_off(lane);
    const uint32_t sBu = smem_u32(sB) + b_lane_off(lane);

    if (tid < 32) s_freq[tid] = powf(10000.0f, -(float)tid / 32.0f);
    if (tid < 384) {
        int r = tid / 3, c = tid - r * 3;
        int row = row0 + r;
        s_pts[tid] = (row < n) ? pts[row * 3 + c] : 0.f;
    }
    __syncthreads();

    const int ar = tid >> 2, acb = (tid & 3) * 4;
    const int bn = tid >> 1, bkq = (tid & 1) * 8;

    auto computeA = [&](int k0, uint32_t* av) {
#pragma unroll
        for (int j = 0; j < 4; j++) {
            int e = k0 + acb + j;
            int c = e >> 6, f = (e & 63) >> 1, s = e & 1;
            float ang = s_pts[ar * 3 + c] * s_freq[f];
            av[j] = f2tf32(s ? cosf(ang) : sinf(ang));
        }
    };

    float acc[2][8][4];
#pragma unroll
    for (int mi = 0; mi < 2; mi++)
#pragma unroll
        for (int ni = 0; ni < 8; ni++)
#pragma unroll
            for (int t = 0; t < 4; t++) acc[mi][ni][t] = 0.f;

    {
        uint32_t av[4];
        computeA(0, av);
        *(uint4*)(sA + ar * SA_P + acb) = make_uint4(av[0], av[1], av[2], av[3]);
        const uint4* g = (const uint4*)(WT + (size_t)bn * 192 + bkq);
        uint4 w0 = g[0], w1 = g[1];
        *(uint4*)(sB + bn * PK + bkq)     = w0;
        *(uint4*)(sB + bn * PK + bkq + 4) = w1;
    }
    __syncthreads();

    for (int k0 = 0; k0 < 192; k0 += 16) {
        const bool nx = (k0 + 16) < 192;
        uint32_t av[4]; uint4 w0, w1;
        if (nx) {
            computeA(k0 + 16, av);
            const uint4* g = (const uint4*)(WT + (size_t)bn * 192 + k0 + 16 + bkq);
            w0 = g[0]; w1 = g[1];
        }
#pragma unroll
        for (int kk = 0; kk < 16; kk += 8) {
            uint32_t afr[2][4], bfr[4][4];
#pragma unroll
            for (int mi = 0; mi < 2; mi++)
                ldsm_x4(afr[mi], sAu + 4u * ((wm + mi * 16) * SA_P + kk));
#pragma unroll
            for (int np = 0; np < 4; np++)
                ldsm_x4(bfr[np], sBu + 4u * ((wn + np * 16) * PK + kk));
#pragma unroll
            for (int mi = 0; mi < 2; mi++)
#pragma unroll
                for (int np = 0; np < 4; np++) {
                    mma_tf32(acc[mi][np * 2],     afr[mi], bfr[np]);
                    mma_tf32(acc[mi][np * 2 + 1], afr[mi], bfr[np] + 2);
                }
        }
        __syncthreads();
        if (nx) {
            *(uint4*)(sA + ar * SA_P + acb) = make_uint4(av[0], av[1], av[2], av[3]);
            *(uint4*)(sB + bn * PK + bkq)     = w0;
            *(uint4*)(sB + bn * PK + bkq + 4) = w1;
            __syncthreads();
        }
    }

#pragma unroll
    for (int mi = 0; mi < 2; mi++) {
        int r0 = row0 + wm + mi * 16 + lr;
        int r1 = r0 + 8;
#pragma unroll
        for (int ni = 0; ni < 8; ni++) {
            int col = wn + ni * 8 + lc * 2;
            float bb0 = bias ? bias[col]     : 0.f;
            float bb1 = bias ? bias[col + 1] : 0.f;
            if (r0 < n) {
                float2 v; v.x = acc[mi][ni][0] + bb0; v.y = acc[mi][ni][1] + bb1;
                *(float2*)(dst + (size_t)r0 * 256 + col) = v;
            }
            if (r1 < n) {
                float2 v; v.x = acc[mi][ni][2] + bb0; v.y = acc[mi][ni][3] + bb1;
                *(float2*)(dst + (size_t)r1 * 256 + col) = v;
            }
        }
    }
}

// ---------------------------------------------------------------------------
// FUSED kernel: per 128-edge block
//   H2 = gelu( gelu(Ay[nbr]+Bx[q]) @ W2 + b2 )       (kept in registers)
//   out = segsum( (H2 @ W3 + b3) * f_y[nbr] )        (shuffle reduction)
// 512 threads = 16 warps. gemm2 layout: (warp&3)*32 m x (warp>>2)*64 n.
// gemm3 layout: (warp>>1)*16 m x (warp&1)*32 n; query == m16 tile.
// ---------------------------------------------------------------------------
__global__ void __launch_bounds__(512) fused_mma_kernel(
    const int*   __restrict__ nbr,
    const float* __restrict__ b2,
    const float* __restrict__ b3,
    const float* __restrict__ fy,
    float*       __restrict__ out)
{
    __shared__ uint32_t sA[128 * SA_P];     // gemm2 A chunks; then H2 chunk staging
    __shared__ uint32_t sB[256 * PK];       // gemm2 B chunks; then W3 chunk staging
    __shared__ int s_nbr[128];

    const int tid  = threadIdx.x;
    const int e0   = blockIdx.x * 128;
    const int warp = tid >> 5, lane = tid & 31;
    const int wm = (warp & 3) * 32, wn = (warp >> 2) * 64;
    const int lr = lane >> 2, lc = lane & 3;
    const uint32_t sAu = smem_u32(sA) + a_lane_off(lane);
    const uint32_t sBu = smem_u32(sB) + b_lane_off(lane);

    if (tid < 128) s_nbr[tid] = nbr[e0 + tid];
    __syncthreads();

    const int ar = tid >> 2, acb = (tid & 3) * 4;
    const float* pA = g_Ay + (size_t)s_nbr[ar] * 256 + acb;
    const float* pB = g_Bx + (size_t)((e0 + ar) >> 4) * 256 + acb;
    const int bn = tid >> 1, bkq = (tid & 1) * 8;

    float acc[2][8][4];
#pragma unroll
    for (int mi = 0; mi < 2; mi++)
#pragma unroll
        for (int ni = 0; ni < 8; ni++)
#pragma unroll
            for (int t = 0; t < 4; t++) acc[mi][ni][t] = 0.f;

    {   // prologue: stage chunk 0
        float4 a = *(const float4*)(pA);
        float4 b = *(const float4*)(pB);
        *(uint4*)(sA + ar * SA_P + acb) = make_uint4(
            f2tf32(gelu_f(a.x + b.x)), f2tf32(gelu_f(a.y + b.y)),
            f2tf32(gelu_f(a.z + b.z)), f2tf32(gelu_f(a.w + b.w)));
        const uint4* g = (const uint4*)(g_W2T + (size_t)bn * 256 + bkq);
        uint4 w0 = g[0], w1 = g[1];
        *(uint4*)(sB + bn * PK + bkq)     = w0;
        *(uint4*)(sB + bn * PK + bkq + 4) = w1;
    }
    __syncthreads();

    // ---- GEMM2 mainloop ----
    for (int k0 = 0; k0 < 256; k0 += 16) {
        const bool nx = (k0 + 16) < 256;
        float4 a, b; uint4 w0, w1;
        if (nx) {
            a = *(const float4*)(pA + k0 + 16);
            b = *(const float4*)(pB + k0 + 16);
            const uint4* g = (const uint4*)(g_W2T + (size_t)bn * 256 + k0 + 16 + bkq);
            w0 = g[0]; w1 = g[1];
        }
#pragma unroll
        for (int kk = 0; kk < 16; kk += 8) {
            uint32_t afr[2][4], bfr[4][4];
#pragma unroll
            for (int mi = 0; mi < 2; mi++)
                ldsm_x4(afr[mi], sAu + 4u * ((wm + mi * 16) * SA_P + kk));
#pragma unroll
            for (int np = 0; np < 4; np++)
                ldsm_x4(bfr[np], sBu + 4u * ((wn + np * 16) * PK + kk));
#pragma unroll
            for (int mi = 0; mi < 2; mi++)
#pragma unroll
                for (int np = 0; np < 4; np++) {
                    mma_tf32(acc[mi][np * 2],     afr[mi], bfr[np]);
                    mma_tf32(acc[mi][np * 2 + 1], afr[mi], bfr[np] + 2);
                }
        }
        __syncthreads();
        if (nx) {
            *(uint4*)(sA + ar * SA_P + acb) = make_uint4(
                f2tf32(gelu_f(a.x + b.x)), f2tf32(gelu_f(a.y + b.y)),
                f2tf32(gelu_f(a.z + b.z)), f2tf32(gelu_f(a.w + b.w)));
            *(uint4*)(sB + bn * PK + bkq)     = w0;
            *(uint4*)(sB + bn * PK + bkq + 4) = w1;
            __syncthreads();
        }
    }

    // ---- H2 finalize in registers: +b2, gelu, tf32 bits ----
    uint32_t hb[2][8][4];
#pragma unroll
    for (int mi = 0; mi < 2; mi++)
#pragma unroll
        for (int ni = 0; ni < 8; ni++) {
            int col = wn + ni * 8 + lc * 2;
            float bb0 = b2[col], bb1 = b2[col + 1];
            hb[mi][ni][0] = f2tf32(gelu_f(acc[mi][ni][0] + bb0));
            hb[mi][ni][1] = f2tf32(gelu_f(acc[mi][ni][1] + bb1));
            hb[mi][ni][2] = f2tf32(gelu_f(acc[mi][ni][2] + bb0));
            hb[mi][ni][3] = f2tf32(gelu_f(acc[mi][ni][3] + bb1));
        }

    // ---- GEMM3 via chunked staging (reuse sA for H2, sB for W3) ----
    const int mw = warp >> 1, nw = warp & 1;    // gemm3 warp layout
    float acc3[4][4];
#pragma unroll
    for (int ni = 0; ni < 4; ni++)
#pragma unroll
        for (int t = 0; t < 4; t++) acc3[ni][t] = 0.f;

    const int w3n = tid >> 3, w3kq = (tid & 7) * 2;   // W3 chunk staging coords
    __syncthreads();   // everyone past gemm2 mainloop before sA reuse

    for (int c = 0; c < 16; c++) {
        // stage H2 chunk cols [c*16, c*16+16): owning warps = (warp>>2 == c>>2)
        if ((warp >> 2) == (c >> 2)) {
            int b = (c & 3) * 2;
#pragma unroll
            for (int mi = 0; mi < 2; mi++) {
                int r0 = wm + mi * 16 + lr;
#pragma unroll
                for (int j = 0; j < 2; j++) {
                    int cc = j * 8 + lc * 2;
                    *(uint2*)(sA + r0 * SA_P + cc) =
                        make_uint2(hb[mi][b + j][0], hb[mi][b + j][1]);
                    *(uint2*)(sA + (r0 + 8) * SA_P + cc) =
                        make_uint2(hb[mi][b + j][2], hb[mi][b + j][3]);
                }
            }
        }
        // stage W3 chunk [64][16] (all threads, 2 words each)
        *(uint2*)(sB + w3n * PK + w3kq) =
            *(const uint2*)(g_W3T + (size_t)w3n * 256 + c * 16 + w3kq);
        __syncthreads();

#pragma unroll
        for (int kk = 0; kk < 16; kk += 8) {
            uint32_t afr[4], bfr[2][4];
            ldsm_x4(afr, sAu + 4u * ((mw * 16) * SA_P + kk));
#pragma unroll
            for (int np = 0; np < 2; np++)
                ldsm_x4(bfr[np], sBu + 4u * ((nw * 32 + np * 16) * PK + kk));
#pragma unroll
            for (int np = 0; np < 2; np++) {
                mma_tf32(acc3[np * 2],     afr, bfr[np]);
                mma_tf32(acc3[np * 2 + 1], afr, bfr[np] + 2);
            }
        }
        __syncthreads();
    }

    // ---- epilogue: +b3, *f_y, 16-edge segsum via shuffles ----
    {
        int r0 = mw * 16 + lr;          // local edge rows r0, r0+8
        int nb0 = s_nbr[r0], nb1 = s_nbr[r0 + 8];
        const int q = blockIdx.x * 8 + mw;
#pragma unroll
        for (int ni = 0; ni < 4; ni++) {
            int col = nw * 32 + ni * 8 + lc * 2;
            float bb0 = b3[col], bb1 = b3[col + 1];
            float2 f0 = *(const float2*)(fy + (size_t)nb0 * 64 + col);
            float2 f1 = *(const float2*)(fy + (size_t)nb1 * 64 + col);
            float s0 = (acc3[ni][0] + bb0) * f0.x + (acc3[ni][2] + bb0) * f1.x;
            float s1 = (acc3[ni][1] + bb1) * f0.y + (acc3[ni][3] + bb1) * f1.y;
#pragma unroll
            for (int off = 4; off <= 16; off <<= 1) {
                s0 += __shfl_xor_sync(0xFFFFFFFFu, s0, off);
                s1 += __shfl_xor_sync(0xFFFFFFFFu, s1, off);
            }
            if (lr == 0)
                *(float2*)(out + (size_t)q * 64 + col) = make_float2(s0, s1);
        }
    }
}

// ---------------------------------------------------------------------------
extern "C" void kernel_launch(void* const* d_in, const int* in_sizes, int n_in,
                              void* d_out, int out_size)
{
    const float* y   = (const float*)d_in[0];
    const float* x   = (const float*)d_in[1];
    const float* f_y = (const float*)d_in[2];
    const int*   nbr = (const int*)d_in[3];
    // d_in[4] = neighbors_row_splits (uniform K=16 -> q = e>>4)
    const float* W1  = (const float*)d_in[5];
    const float* b1  = (const float*)d_in[6];
    const float* W2  = (const float*)d_in[7];
    const float* b2  = (const float*)d_in[8];
    const float* W3  = (const float*)d_in[9];
    const float* b3  = (const float*)d_in[10];
    float* out = (float*)d_out;

    dim3 tb(32, 8);
    transpose_cvt_kernel<<<dim3(8, 6), tb>>>(W1,             192, 256, 0);
    transpose_cvt_kernel<<<dim3(8, 6), tb>>>(W1 + 192 * 256, 192, 256, 1);
    transpose_cvt_kernel<<<dim3(8, 8), tb>>>(W2,             256, 256, 2);
    transpose_cvt_kernel<<<dim3(2, 8), tb>>>(W3,             256,  64, 3);

    embed_mma_kernel<<<(N_Y + 127) / 128, 512>>>(y, nullptr, 0, N_Y);
    embed_mma_kernel<<<(N_X + 127) / 128, 512>>>(x, b1, 1, N_X);
    fused_mma_kernel<<<NE / 128, 512>>>(nbr, b2, b3, f_y, out);
}

// round 6
// speedup vs baseline: 1.2159x; 1.2159x over previous
#include <cuda_runtime.h>
#include <math.h>
#include <stdint.h>

#define N_Y   100000
#define N_X   20000
#define KNN   16
#define NE    (N_X * KNN)      // 320000 edges
#define HID   256
#define CIN   64

// Scratch (device globals: allocation-free contract)
__device__ float    g_Ay[(size_t)N_Y * HID];
__device__ float    g_Bx[(size_t)N_X * HID];
__device__ uint32_t g_H2u[(size_t)NE * HID];       // tf32 bits
// transposed + tf32-converted weights, [n][k] dense
__device__ uint32_t g_W1aT[256 * 192];
__device__ uint32_t g_W1bT[256 * 192];
__device__ uint32_t g_W2T[256 * 256];
__device__ uint32_t g_W3T[64 * 256];

__device__ __forceinline__ float gelu_f(float v) {
    return 0.5f * v * (1.0f + erff(v * 0.70710678118654752f));
}
__device__ __forceinline__ uint32_t f2tf32(float x) {
    uint32_t r;
    asm("cvt.rna.tf32.f32 %0, %1;" : "=r"(r) : "f"(x));
    return r;
}
__device__ __forceinline__ void mma_tf32(float* d, const uint32_t* a, const uint32_t* b) {
    asm volatile(
        "mma.sync.aligned.m16n8k8.row.col.f32.tf32.tf32.f32 "
        "{%0,%1,%2,%3}, {%4,%5,%6,%7}, {%8,%9}, {%0,%1,%2,%3};\n"
        : "+f"(d[0]), "+f"(d[1]), "+f"(d[2]), "+f"(d[3])
        : "r"(a[0]), "r"(a[1]), "r"(a[2]), "r"(a[3]), "r"(b[0]), "r"(b[1]));
}
__device__ __forceinline__ void ldsm_x4(uint32_t* r, uint32_t saddr) {
    asm volatile("ldmatrix.sync.aligned.m8n8.x4.shared.b16 {%0,%1,%2,%3}, [%4];"
                 : "=r"(r[0]), "=r"(r[1]), "=r"(r[2]), "=r"(r[3]) : "r"(saddr));
}
__device__ __forceinline__ uint32_t smem_u32(const void* p) {
    return (uint32_t)__cvta_generic_to_shared(p);
}
__device__ __forceinline__ void cpa16(uint32_t dst, const void* src) {
    asm volatile("cp.async.ca.shared.global [%0], [%1], 16;\n" :: "r"(dst), "l"(src));
}
#define CPA_COMMIT asm volatile("cp.async.commit_group;\n")
#define CPA_WAIT0  asm volatile("cp.async.wait_group 0;\n")

// XOR-swizzled [R][32] word tile: word(r,c) = r*32 + (((c>>2)^(r&7))<<2) + (c&3)
__device__ __forceinline__ uint32_t* swp(uint32_t* base, int r, int cw) {
    return base + r * 32 + ((((cw >> 2) ^ (r & 7)) << 2));
}
// ldmatrix byte address helpers (row&7 == lane&7 because tile bases are mult of 16)
// A (m16k8): row m0+(l&15), cbank (kk>>2)+(l>>4)
__device__ __forceinline__ uint32_t ldsmA(uint32_t rowbase, int m0, int kk, int lane) {
    return rowbase + (uint32_t)m0 * 128u + (uint32_t)(((((kk) >> 2) + (lane >> 4)) ^ (lane & 7)) << 4);
}
// B (two n8xk8): row n0+(l&7)+((l>>4)<<3), cbank (kk>>2)+((l>>3)&1)
__device__ __forceinline__ uint32_t ldsmB(uint32_t rowbase, int n0, int kk, int lane) {
    return rowbase + (uint32_t)n0 * 128u + (uint32_t)(((((kk) >> 2) + ((lane >> 3) & 1)) ^ (lane & 7)) << 4);
}

// ---------------------------------------------------------------------------
// Weight transpose + tf32 convert: src fp32 [K][N] -> dst u32 [N][K]
// ---------------------------------------------------------------------------
__device__ __forceinline__ uint32_t* sel_dst(int w) {
    return w == 0 ? g_W1aT : w == 1 ? g_W1bT : w == 2 ? g_W2T : g_W3T;
}
__global__ void transpose_cvt_kernel(const float* __restrict__ src, int K, int N, int w)
{
    __shared__ float t[32][33];
    uint32_t* dst = sel_dst(w);
    int k0 = blockIdx.y * 32, n0 = blockIdx.x * 32;
    int tx = threadIdx.x, ty = threadIdx.y;   // 32 x 8
#pragma unroll
    for (int i = 0; i < 32; i += 8)
        t[ty + i][tx] = src[(size_t)(k0 + ty + i) * N + n0 + tx];
    __syncthreads();
#pragma unroll
    for (int i = 0; i < 32; i += 8)
        dst[(size_t)(n0 + ty + i) * K + k0 + tx] = f2tf32(t[tx][ty + i]);
}

// ---------------------------------------------------------------------------
// Embed + GEMM1: dst = emb(pts) @ W (+bias).  BM=128, BN=256, K=192, BK=32.
// 512 threads = 16 warps (4m x 4n), warp tile 32x64. smem = 48KB exactly.
// ---------------------------------------------------------------------------
__global__ void __launch_bounds__(512) embed_mma_kernel(
    const float* __restrict__ pts,
    const float* __restrict__ bias,
    int which, int n)
{
    __shared__ uint32_t sA[128 * 32];   // 16384 B
    __shared__ uint32_t sB[256 * 32];   // 32768 B

    const uint32_t* WT = which ? g_W1bT : g_W1aT;
    float* dst = which ? g_Bx : g_Ay;
    const int tid  = threadIdx.x;
    const int row0 = blockIdx.x * 128;
    const int warp = tid >> 5, lane = tid & 31;
    const int wm = (warp & 3) * 32, wn = (warp >> 2) * 64;
    const int lr = lane >> 2, lc = lane & 3;
    const uint32_t sAr = smem_u32(sA) + (lane & 15) * 128;
    const uint32_t sBr = smem_u32(sB) + ((lane & 7) + ((lane >> 4) << 3)) * 128;

    // A staging: 8 embedding elems/thread
    const int ar = tid >> 2, cb = (tid & 3) * 8;
    const int arow = row0 + ar;
    float3 p = make_float3(0.f, 0.f, 0.f);
    if (arow < n) { p.x = pts[arow * 3]; p.y = pts[arow * 3 + 1]; p.z = pts[arow * 3 + 2]; }
    // B staging: 16 words/thread via cp.async
    const int bn = tid >> 1, bw = (tid & 1) * 16;

    auto computeA = [&](int k0, uint32_t* av) {
        int e0e = k0 + cb;                 // 8 consecutive e, same coord c
        int c = e0e >> 6;
        float pc = c == 0 ? p.x : (c == 1 ? p.y : p.z);
        int fb = (e0e & 63) >> 1;
#pragma unroll
        for (int i = 0; i < 4; i++) {
            float freq = exp2f(-0.41524101f * (float)(fb + i));
            float s, cf;
            sincosf(pc * freq, &s, &cf);
            av[i * 2]     = f2tf32(s);
            av[i * 2 + 1] = f2tf32(cf);
        }
    };
    auto stageB = [&](int k0) {
#pragma unroll
        for (int j = 0; j < 4; j++)
            cpa16(smem_u32(swp(sB, bn, bw + j * 4)),
                  WT + (size_t)bn * 192 + k0 + bw + j * 4);
        CPA_COMMIT;
    };

    float acc[2][8][4];
#pragma unroll
    for (int mi = 0; mi < 2; mi++)
#pragma unroll
        for (int ni = 0; ni < 8; ni++)
#pragma unroll
            for (int t = 0; t < 4; t++) acc[mi][ni][t] = 0.f;

    {   // prologue
        stageB(0);
        uint32_t av[8];
        computeA(0, av);
        uint32_t* d0 = swp(sA, ar, cb);
        uint32_t* d1 = swp(sA, ar, cb + 4);
        d0[0] = av[0]; d0[1] = av[1]; d0[2] = av[2]; d0[3] = av[3];
        d1[0] = av[4]; d1[1] = av[5]; d1[2] = av[6]; d1[3] = av[7];
        CPA_WAIT0;
    }
    __syncthreads();

    for (int k0 = 0; k0 < 192; k0 += 32) {
        const bool nx = (k0 + 32) < 192;
        uint32_t av[8];
        if (nx) computeA(k0 + 32, av);
#pragma unroll
        for (int kk = 0; kk < 32; kk += 8) {
            uint32_t afr[2][4], bfr[4][4];
#pragma unroll
            for (int mi = 0; mi < 2; mi++)
                ldsm_x4(afr[mi], ldsmA(sAr, wm + mi * 16, kk, lane));
#pragma unroll
            for (int np = 0; np < 4; np++)
                ldsm_x4(bfr[np], ldsmB(sBr, wn + np * 16, kk, lane));
#pragma unroll
            for (int mi = 0; mi < 2; mi++)
#pragma unroll
                for (int np = 0; np < 4; np++) {
                    mma_tf32(acc[mi][np * 2],     afr[mi], bfr[np]);
                    mma_tf32(acc[mi][np * 2 + 1], afr[mi], bfr[np] + 2);
                }
        }
        __syncthreads();
        if (nx) {
            uint32_t* d0 = swp(sA, ar, cb);
            uint32_t* d1 = swp(sA, ar, cb + 4);
            d0[0] = av[0]; d0[1] = av[1]; d0[2] = av[2]; d0[3] = av[3];
            d1[0] = av[4]; d1[1] = av[5]; d1[2] = av[6]; d1[3] = av[7];
            stageB(k0 + 32);
            CPA_WAIT0;
            __syncthreads();
        }
    }

#pragma unroll
    for (int mi = 0; mi < 2; mi++) {
        int r0 = row0 + wm + mi * 16 + lr;
        int r1 = r0 + 8;
#pragma unroll
        for (int ni = 0; ni < 8; ni++) {
            int col = wn + ni * 8 + lc * 2;
            float bb0 = bias ? bias[col]     : 0.f;
            float bb1 = bias ? bias[col + 1] : 0.f;
            if (r0 < n) {
                float2 v; v.x = acc[mi][ni][0] + bb0; v.y = acc[mi][ni][1] + bb1;
                *(float2*)(dst + (size_t)r0 * 256 + col) = v;
            }
            if (r1 < n) {
                float2 v; v.x = acc[mi][ni][2] + bb0; v.y = acc[mi][ni][3] + bb1;
                *(float2*)(dst + (size_t)r1 * 256 + col) = v;
            }
        }
    }
}

// ---------------------------------------------------------------------------
// GEMM2 (fused gather+gelu): H2u = tf32(gelu( gelu(Ay[nbr]+Bx[q]) @ W2 + b2 ))
// BM=128, BN=256, K=256, BK=32. 512 threads. smem = 48KB exactly.
// ---------------------------------------------------------------------------
__global__ void __launch_bounds__(512) gemm2_mma_kernel(
    const int*   __restrict__ nbr,
    const float* __restrict__ b2)
{
    __shared__ uint32_t sA[128 * 32];
    __shared__ uint32_t sB[256 * 32];

    const int tid  = threadIdx.x;
    const int e0   = blockIdx.x * 128;
    const int warp = tid >> 5, lane = tid & 31;
    const int wm = (warp & 3) * 32, wn = (warp >> 2) * 64;
    const int lr = lane >> 2, lc = lane & 3;
    const uint32_t sAr = smem_u32(sA) + (lane & 15) * 128;
    const uint32_t sBr = smem_u32(sB) + ((lane & 7) + ((lane >> 4) << 3)) * 128;

    const int ar = tid >> 2, cb = (tid & 3) * 8;
    const int nb = nbr[e0 + ar];
    const float* pA = g_Ay + (size_t)nb * 256 + cb;
    const float* pB = g_Bx + (size_t)((e0 + ar) >> 4) * 256 + cb;
    const int bn = tid >> 1, bw = (tid & 1) * 16;

    auto stageB = [&](int k0) {
#pragma unroll
        for (int j = 0; j < 4; j++)
            cpa16(smem_u32(swp(sB, bn, bw + j * 4)),
                  g_W2T + (size_t)bn * 256 + k0 + bw + j * 4);
        CPA_COMMIT;
    };
    auto storeA = [&](const float4& a0, const float4& a1,
                      const float4& b0, const float4& b1) {
        uint32_t* d0 = swp(sA, ar, cb);
        uint32_t* d1 = swp(sA, ar, cb + 4);
        d0[0] = f2tf32(gelu_f(a0.x + b0.x));
        d0[1] = f2tf32(gelu_f(a0.y + b0.y));
        d0[2] = f2tf32(gelu_f(a0.z + b0.z));
        d0[3] = f2tf32(gelu_f(a0.w + b0.w));
        d1[0] = f2tf32(gelu_f(a1.x + b1.x));
        d1[1] = f2tf32(gelu_f(a1.y + b1.y));
        d1[2] = f2tf32(gelu_f(a1.z + b1.z));
        d1[3] = f2tf32(gelu_f(a1.w + b1.w));
    };

    float acc[2][8][4];
#pragma unroll
    for (int mi = 0; mi < 2; mi++)
#pragma unroll
        for (int ni = 0; ni < 8; ni++)
#pragma unroll
            for (int t = 0; t < 4; t++) acc[mi][ni][t] = 0.f;

    {   // prologue
        stageB(0);
        float4 a0 = *(const float4*)(pA), a1 = *(const float4*)(pA + 4);
        float4 b0 = *(const float4*)(pB), b1 = *(const float4*)(pB + 4);
        storeA(a0, a1, b0, b1);
        CPA_WAIT0;
    }
    __syncthreads();

    for (int k0 = 0; k0 < 256; k0 += 32) {
        const bool nx = (k0 + 32) < 256;
        float4 a0, a1, b0, b1;
        if (nx) {
            a0 = *(const float4*)(pA + k0 + 32); a1 = *(const float4*)(pA + k0 + 36);
            b0 = *(const float4*)(pB + k0 + 32); b1 = *(const float4*)(pB + k0 + 36);
        }
#pragma unroll
        for (int kk = 0; kk < 32; kk += 8) {
            uint32_t afr[2][4], bfr[4][4];
#pragma unroll
            for (int mi = 0; mi < 2; mi++)
                ldsm_x4(afr[mi], ldsmA(sAr, wm + mi * 16, kk, lane));
#pragma unroll
            for (int np = 0; np < 4; np++)
                ldsm_x4(bfr[np], ldsmB(sBr, wn + np * 16, kk, lane));
#pragma unroll
            for (int mi = 0; mi < 2; mi++)
#pragma unroll
                for (int np = 0; np < 4; np++) {
                    mma_tf32(acc[mi][np * 2],     afr[mi], bfr[np]);
                    mma_tf32(acc[mi][np * 2 + 1], afr[mi], bfr[np] + 2);
                }
        }
        __syncthreads();
        if (nx) {
            storeA(a0, a1, b0, b1);
            stageB(k0 + 32);
            CPA_WAIT0;
            __syncthreads();
        }
    }

    // epilogue: +b2, gelu, tf32-store
#pragma unroll
    for (int mi = 0; mi < 2; mi++) {
        int r0 = e0 + wm + mi * 16 + lr;
#pragma unroll
        for (int ni = 0; ni < 8; ni++) {
            int col = wn + ni * 8 + lc * 2;
            float bb0 = b2[col], bb1 = b2[col + 1];
            uint2 v0, v1;
            v0.x = f2tf32(gelu_f(acc[mi][ni][0] + bb0));
            v0.y = f2tf32(gelu_f(acc[mi][ni][1] + bb1));
            v1.x = f2tf32(gelu_f(acc[mi][ni][2] + bb0));
            v1.y = f2tf32(gelu_f(acc[mi][ni][3] + bb1));
            *(uint2*)(g_H2u + (size_t)r0 * 256 + col) = v0;
            *(uint2*)(g_H2u + (size_t)(r0 + 8) * 256 + col) = v1;
        }
    }
}

// ---------------------------------------------------------------------------
// GEMM3 + segsum: out = segsum( (H2 @ W3 + b3) * f_y[nbr] )
// BM=128, BN=64, K=256, BK=32. 256 threads = 8 m-warps (m16 x n64 each).
// Query == m16 tile -> shuffle reduction, no smem staging for the segsum.
// ---------------------------------------------------------------------------
__global__ void __launch_bounds__(256) gemm3_mma_kernel(
    const int*   __restrict__ nbr,
    const float* __restrict__ b3,
    const float* __restrict__ fy,
    float*       __restrict__ out)
{
    __shared__ uint32_t sA[128 * 32];   // 16384
    __shared__ uint32_t sB3[64 * 32];   // 8192
    __shared__ int s_nbr[128];

    const int tid  = threadIdx.x;
    const int e0   = blockIdx.x * 128;
    const int warp = tid >> 5, lane = tid & 31;
    const int lr = lane >> 2, lc = lane & 3;
    const uint32_t sAr = smem_u32(sA) + (lane & 15) * 128;
    const uint32_t sBr = smem_u32(sB3) + ((lane & 7) + ((lane >> 4) << 3)) * 128;

    if (tid < 128) s_nbr[tid] = nbr[e0 + tid];

    const int ar = tid >> 1, cw = (tid & 1) * 16;   // A: 16 words/thread
    const uint32_t* pA = g_H2u + (size_t)(e0 + ar) * 256 + cw;
    const int b3n = tid >> 2, b3w = (tid & 3) * 8;  // B: 8 words/thread

    auto stageB = [&](int k0) {
        cpa16(smem_u32(swp(sB3, b3n, b3w)),
              g_W3T + (size_t)b3n * 256 + k0 + b3w);
        cpa16(smem_u32(swp(sB3, b3n, b3w + 4)),
              g_W3T + (size_t)b3n * 256 + k0 + b3w + 4);
        CPA_COMMIT;
    };
    auto storeA = [&](const uint4* v) {
#pragma unroll
        for (int j = 0; j < 4; j++)
            *(uint4*)swp(sA, ar, cw + j * 4) = v[j];
    };

    float acc3[8][4];
#pragma unroll
    for (int ni = 0; ni < 8; ni++)
#pragma unroll
        for (int t = 0; t < 4; t++) acc3[ni][t] = 0.f;

    {   // prologue
        stageB(0);
        uint4 v[4];
#pragma unroll
        for (int j = 0; j < 4; j++) v[j] = *(const uint4*)(pA + j * 4);
        storeA(v);
        CPA_WAIT0;
    }
    __syncthreads();

    for (int k0 = 0; k0 < 256; k0 += 32) {
        const bool nx = (k0 + 32) < 256;
        uint4 v[4];
        if (nx) {
#pragma unroll
            for (int j = 0; j < 4; j++) v[j] = *(const uint4*)(pA + k0 + 32 + j * 4);
        }
#pragma unroll
        for (int kk = 0; kk < 32; kk += 8) {
            uint32_t afr[4], bfr[4][4];
            ldsm_x4(afr, ldsmA(sAr, warp * 16, kk, lane));
#pragma unroll
            for (int np = 0; np < 4; np++)
                ldsm_x4(bfr[np], ldsmB(sBr, np * 16, kk, lane));
#pragma unroll
            for (int np = 0; np < 4; np++) {
                mma_tf32(acc3[np * 2],     afr, bfr[np]);
                mma_tf32(acc3[np * 2 + 1], afr, bfr[np] + 2);
            }
        }
        __syncthreads();
        if (nx) {
            storeA(v);
            stageB(k0 + 32);
            CPA_WAIT0;
            __syncthreads();
        }
    }

    // epilogue: +b3, *f_y, 16-edge segsum via shuffles (query == m16 tile)
    {
        int r0 = warp * 16 + lr;
        int nb0 = s_nbr[r0], nb1 = s_nbr[r0 + 8];
        const int q = blockIdx.x * 8 + warp;
#pragma unroll
        for (int ni = 0; ni < 8; ni++) {
            int col = ni * 8 + lc * 2;
            float bb0 = b3[col], bb1 = b3[col + 1];
            float2 f0 = *(const float2*)(fy + (size_t)nb0 * 64 + col);
            float2 f1 = *(const float2*)(fy + (size_t)nb1 * 64 + col);
            float s0 = (acc3[ni][0] + bb0) * f0.x + (acc3[ni][2] + bb0) * f1.x;
            float s1 = (acc3[ni][1] + bb1) * f0.y + (acc3[ni][3] + bb1) * f1.y;
#pragma unroll
            for (int off = 4; off <= 16; off <<= 1) {
                s0 += __shfl_xor_sync(0xFFFFFFFFu, s0, off);
                s1 += __shfl_xor_sync(0xFFFFFFFFu, s1, off);
            }
            if (lr == 0)
                *(float2*)(out + (size_t)q * 64 + col) = make_float2(s0, s1);
        }
    }
}

// ---------------------------------------------------------------------------
extern "C" void kernel_launch(void* const* d_in, const int* in_sizes, int n_in,
                              void* d_out, int out_size)
{
    const float* y   = (const float*)d_in[0];
    const float* x   = (const float*)d_in[1];
    const float* f_y = (const float*)d_in[2];
    const int*   nbr = (const int*)d_in[3];
    // d_in[4] = neighbors_row_splits (uniform K=16 -> q = e>>4)
    const float* W1  = (const float*)d_in[5];
    const float* b1  = (const float*)d_in[6];
    const float* W2  = (const float*)d_in[7];
    const float* b2  = (const float*)d_in[8];
    const float* W3  = (const float*)d_in[9];
    const float* b3  = (const float*)d_in[10];
    float* out = (float*)d_out;

    dim3 tb(32, 8);
    transpose_cvt_kernel<<<dim3(8, 6), tb>>>(W1,             192, 256, 0);
    transpose_cvt_kernel<<<dim3(8, 6), tb>>>(W1 + 192 * 256, 192, 256, 1);
    transpose_cvt_kernel<<<dim3(8, 8), tb>>>(W2,             256, 256, 2);
    transpose_cvt_kernel<<<dim3(2, 8), tb>>>(W3,             256,  64, 3);

    embed_mma_kernel<<<(N_Y + 127) / 128, 512>>>(y, nullptr, 0, N_Y);
    embed_mma_kernel<<<(N_X + 127) / 128, 512>>>(x, b1, 1, N_X);
    gemm2_mma_kernel<<<NE / 128, 512>>>(nbr, b2);
    gemm3_mma_kernel<<<NE / 128, 256>>>(nbr, b3, f_y, out);
}

// round 7
// speedup vs baseline: 1.8307x; 1.5057x over previous
#include <cuda_runtime.h>
#include <cuda_fp16.h>
#include <math.h>
#include <stdint.h>

#define N_Y   100000
#define N_X   20000
#define KNN   16
#define NE    (N_X * KNN)      // 320000 edges
#define HID   256
#define CIN   64

// Scratch (device globals: allocation-free contract)
__device__ float   g_Ay[(size_t)N_Y * HID];
__device__ float   g_Bx[(size_t)N_X * HID];
__device__ __half  g_H2h[(size_t)NE * HID];
// transposed + fp16-converted weights, [n][k] dense
__device__ __half  g_W1aT[256 * 192];
__device__ __half  g_W1bT[256 * 192];
__device__ __half  g_W2T[256 * 256];
__device__ __half  g_W3T[64 * 256];

__device__ __forceinline__ float gelu_f(float v) {
    return 0.5f * v * (1.0f + erff(v * 0.70710678118654752f));
}
__device__ __forceinline__ uint32_t pack_h2(float lo, float hi) {
    __half2 h = __floats2half2_rn(lo, hi);
    return *reinterpret_cast<uint32_t*>(&h);
}
// D += A(f16) * B(f16); m16n8k16, row.col, fp32 accum
__device__ __forceinline__ void mma_f16(float* d, const uint32_t* a, const uint32_t* b) {
    asm volatile(
        "mma.sync.aligned.m16n8k16.row.col.f32.f16.f16.f32 "
        "{%0,%1,%2,%3}, {%4,%5,%6,%7}, {%8,%9}, {%0,%1,%2,%3};\n"
        : "+f"(d[0]), "+f"(d[1]), "+f"(d[2]), "+f"(d[3])
        : "r"(a[0]), "r"(a[1]), "r"(a[2]), "r"(a[3]), "r"(b[0]), "r"(b[1]));
}
__device__ __forceinline__ void ldsm_x4(uint32_t* r, uint32_t saddr) {
    asm volatile("ldmatrix.sync.aligned.m8n8.x4.shared.b16 {%0,%1,%2,%3}, [%4];"
                 : "=r"(r[0]), "=r"(r[1]), "=r"(r[2]), "=r"(r[3]) : "r"(saddr));
}
__device__ __forceinline__ uint32_t smem_u32(const void* p) {
    return (uint32_t)__cvta_generic_to_shared(p);
}
__device__ __forceinline__ void cpa16(uint32_t dst, const void* src) {
    asm volatile("cp.async.ca.shared.global [%0], [%1], 16;\n" :: "r"(dst), "l"(src));
}
#define CPA_COMMIT asm volatile("cp.async.commit_group;\n")
#define CPA_WAIT0  asm volatile("cp.async.wait_group 0;\n")

// fp16 tile: row = 64 halves = 128 B; XOR swizzle on 16B chunks.
// byte offset of (row r, half-col c [mult of 8]):
__device__ __forceinline__ uint32_t swb(int r, int c) {
    return (uint32_t)(r * 128) + (uint32_t)((((c >> 3) ^ (r & 7)) << 4));
}
// ldmatrix addresses (b16):
// A m16k16: lanes 0-15 rows m0+.., lanes>>4 pick k-half (8 cols = 1 chunk)
__device__ __forceinline__ uint32_t ldsmA_addr(uint32_t base, int m0, int kk, int lane) {
    int r = m0 + (lane & 15);
    int ch = (kk >> 3) + (lane >> 4);
    return base + (uint32_t)(r * 128) + (uint32_t)(((ch ^ (r & 7)) << 4));
}
// B (two n8xk16 frags): rows n0+(l&7)+((l>>4)<<3), k-half (l>>3)&1
__device__ __forceinline__ uint32_t ldsmB_addr(uint32_t base, int n0, int kk, int lane) {
    int r = n0 + (lane & 7) + ((lane >> 4) << 3);
    int ch = (kk >> 3) + ((lane >> 3) & 1);
    return base + (uint32_t)(r * 128) + (uint32_t)(((ch ^ (r & 7)) << 4));
}

// ---------------------------------------------------------------------------
// Weight transpose + fp16 convert: src fp32 [K][N] -> dst half [N][K]
// ---------------------------------------------------------------------------
__device__ __forceinline__ __half* sel_dst(int w) {
    return w == 0 ? g_W1aT : w == 1 ? g_W1bT : w == 2 ? g_W2T : g_W3T;
}
__global__ void transpose_cvt_kernel(const float* __restrict__ src, int K, int N, int w)
{
    __shared__ float t[32][33];
    __half* dst = sel_dst(w);
    int k0 = blockIdx.y * 32, n0 = blockIdx.x * 32;
    int tx = threadIdx.x, ty = threadIdx.y;   // 32 x 8
#pragma unroll
    for (int i = 0; i < 32; i += 8)
        t[ty + i][tx] = src[(size_t)(k0 + ty + i) * N + n0 + tx];
    __syncthreads();
#pragma unroll
    for (int i = 0; i < 32; i += 8)
        dst[(size_t)(n0 + ty + i) * K + k0 + tx] = __float2half(t[tx][ty + i]);
}

// ---------------------------------------------------------------------------
// Embed + GEMM1: dst = emb(pts) @ W (+bias).  BM=128, BN=256, K=192, BK=64.
// 512 threads = 16 warps (4m x 4n), warp tile 32x64. smem = 48KB.
// ---------------------------------------------------------------------------
__global__ void __launch_bounds__(512) embed_mma_kernel(
    const float* __restrict__ pts,
    const float* __restrict__ bias,
    int which, int n)
{
    __shared__ __align__(128) char sA[128 * 128];   // 16 KB (128 x 64 half)
    __shared__ __align__(128) char sB[256 * 128];   // 32 KB (256 x 64 half)

    const __half* WT = which ? g_W1bT : g_W1aT;
    float* dst = which ? g_Bx : g_Ay;
    const int tid  = threadIdx.x;
    const int row0 = blockIdx.x * 128;
    const int warp = tid >> 5, lane = tid & 31;
    const int wm = (warp & 3) * 32, wn = (warp >> 2) * 64;
    const int lr = lane >> 2, lc = lane & 3;
    const uint32_t sAu = smem_u32(sA), sBu = smem_u32(sB);

    // A staging: 16 halves/thread (row ar, cols cb..cb+15)
    const int ar = tid >> 2, cb = (tid & 3) * 16;
    const int arow = row0 + ar;
    float3 p = make_float3(0.f, 0.f, 0.f);
    if (arow < n) { p.x = pts[arow * 3]; p.y = pts[arow * 3 + 1]; p.z = pts[arow * 3 + 2]; }
    // B staging: 32 halves/thread via cp.async
    const int bn = tid >> 1, bw = (tid & 1) * 32;

    auto computeA = [&](int k0, uint32_t* av) {   // av[8] = 8 half2 (sin,cos pairs)
        int e0e = k0 + cb;
        int c = e0e >> 6;
        float pc = c == 0 ? p.x : (c == 1 ? p.y : p.z);
        int fb = (e0e & 63) >> 1;
#pragma unroll
        for (int i = 0; i < 8; i++) {
            float freq = exp2f(-0.41524101186f * (float)(fb + i));
            float s, cf;
            sincosf(pc * freq, &s, &cf);
            av[i] = pack_h2(s, cf);
        }
    };
    auto storeA = [&](const uint32_t* av) {
        *(uint4*)(sA + swb(ar, cb))     = make_uint4(av[0], av[1], av[2], av[3]);
        *(uint4*)(sA + swb(ar, cb + 8)) = make_uint4(av[4], av[5], av[6], av[7]);
    };
    auto stageB = [&](int k0) {
#pragma unroll
        for (int j = 0; j < 4; j++)
            cpa16(sBu + swb(bn, bw + j * 8), WT + (size_t)bn * 192 + k0 + bw + j * 8);
        CPA_COMMIT;
    };

    float acc[2][8][4];
#pragma unroll
    for (int mi = 0; mi < 2; mi++)
#pragma unroll
        for (int ni = 0; ni < 8; ni++)
#pragma unroll
            for (int t = 0; t < 4; t++) acc[mi][ni][t] = 0.f;

    {   // prologue
        stageB(0);
        uint32_t av[8];
        computeA(0, av);
        storeA(av);
        CPA_WAIT0;
    }
    __syncthreads();

    for (int k0 = 0; k0 < 192; k0 += 64) {
        const bool nx = (k0 + 64) < 192;
        uint32_t av[8];
        if (nx) computeA(k0 + 64, av);
#pragma unroll
        for (int kk = 0; kk < 64; kk += 16) {
            uint32_t afr[2][4], bfr[4][4];
#pragma unroll
            for (int mi = 0; mi < 2; mi++)
                ldsm_x4(afr[mi], ldsmA_addr(sAu, wm + mi * 16, kk, lane));
#pragma unroll
            for (int np = 0; np < 4; np++)
                ldsm_x4(bfr[np], ldsmB_addr(sBu, wn + np * 16, kk, lane));
#pragma unroll
            for (int mi = 0; mi < 2; mi++)
#pragma unroll
                for (int np = 0; np < 4; np++) {
                    mma_f16(acc[mi][np * 2],     afr[mi], bfr[np]);
                    mma_f16(acc[mi][np * 2 + 1], afr[mi], bfr[np] + 2);
                }
        }
        __syncthreads();
        if (nx) {
            storeA(av);
            stageB(k0 + 64);
            CPA_WAIT0;
            __syncthreads();
        }
    }

#pragma unroll
    for (int mi = 0; mi < 2; mi++) {
        int r0 = row0 + wm + mi * 16 + lr;
        int r1 = r0 + 8;
#pragma unroll
        for (int ni = 0; ni < 8; ni++) {
            int col = wn + ni * 8 + lc * 2;
            float bb0 = bias ? bias[col]     : 0.f;
            float bb1 = bias ? bias[col + 1] : 0.f;
            if (r0 < n) {
                float2 v; v.x = acc[mi][ni][0] + bb0; v.y = acc[mi][ni][1] + bb1;
                *(float2*)(dst + (size_t)r0 * 256 + col) = v;
            }
            if (r1 < n) {
                float2 v; v.x = acc[mi][ni][2] + bb0; v.y = acc[mi][ni][3] + bb1;
                *(float2*)(dst + (size_t)r1 * 256 + col) = v;
            }
        }
    }
}

// ---------------------------------------------------------------------------
// GEMM2 (fused gather+gelu): H2h = h( gelu( gelu(Ay[nbr]+Bx[q]) @ W2 + b2 ) )
// BM=128, BN=256, K=256, BK=64. 512 threads. smem = 48KB.
// ---------------------------------------------------------------------------
__global__ void __launch_bounds__(512) gemm2_mma_kernel(
    const int*   __restrict__ nbr,
    const float* __restrict__ b2)
{
    __shared__ __align__(128) char sA[128 * 128];
    __shared__ __align__(128) char sB[256 * 128];

    const int tid  = threadIdx.x;
    const int e0   = blockIdx.x * 128;
    const int warp = tid >> 5, lane = tid & 31;
    const int wm = (warp & 3) * 32, wn = (warp >> 2) * 64;
    const int lr = lane >> 2, lc = lane & 3;
    const uint32_t sAu = smem_u32(sA), sBu = smem_u32(sB);

    const int ar = tid >> 2, cb = (tid & 3) * 16;
    const int nb = nbr[e0 + ar];
    const float* pA = g_Ay + (size_t)nb * 256 + cb;
    const float* pB = g_Bx + (size_t)((e0 + ar) >> 4) * 256 + cb;
    const int bn = tid >> 1, bw = (tid & 1) * 32;

    auto stageB = [&](int k0) {
#pragma unroll
        for (int j = 0; j < 4; j++)
            cpa16(sBu + swb(bn, bw + j * 8), g_W2T + (size_t)bn * 256 + k0 + bw + j * 8);
        CPA_COMMIT;
    };
    auto storeA = [&](const float4* a, const float4* b) {
        uint32_t w[8];
#pragma unroll
        for (int j = 0; j < 4; j++) {
            w[j * 2]     = pack_h2(gelu_f(a[j].x + b[j].x), gelu_f(a[j].y + b[j].y));
            w[j * 2 + 1] = pack_h2(gelu_f(a[j].z + b[j].z), gelu_f(a[j].w + b[j].w));
        }
        *(uint4*)(sA + swb(ar, cb))     = make_uint4(w[0], w[1], w[2], w[3]);
        *(uint4*)(sA + swb(ar, cb + 8)) = make_uint4(w[4], w[5], w[6], w[7]);
    };

    float acc[2][8][4];
#pragma unroll
    for (int mi = 0; mi < 2; mi++)
#pragma unroll
        for (int ni = 0; ni < 8; ni++)
#pragma unroll
            for (int t = 0; t < 4; t++) acc[mi][ni][t] = 0.f;

    {   // prologue
        stageB(0);
        float4 a[4], b[4];
#pragma unroll
        for (int j = 0; j < 4; j++) {
            a[j] = *(const float4*)(pA + j * 4);
            b[j] = *(const float4*)(pB + j * 4);
        }
        storeA(a, b);
        CPA_WAIT0;
    }
    __syncthreads();

    for (int k0 = 0; k0 < 256; k0 += 64) {
        const bool nx = (k0 + 64) < 256;
        float4 a[4], b[4];
        if (nx) {
#pragma unroll
            for (int j = 0; j < 4; j++) {
                a[j] = *(const float4*)(pA + k0 + 64 + j * 4);
                b[j] = *(const float4*)(pB + k0 + 64 + j * 4);
            }
        }
#pragma unroll
        for (int kk = 0; kk < 64; kk += 16) {
            uint32_t afr[2][4], bfr[4][4];
#pragma unroll
            for (int mi = 0; mi < 2; mi++)
                ldsm_x4(afr[mi], ldsmA_addr(sAu, wm + mi * 16, kk, lane));
#pragma unroll
            for (int np = 0; np < 4; np++)
                ldsm_x4(bfr[np], ldsmB_addr(sBu, wn + np * 16, kk, lane));
#pragma unroll
            for (int mi = 0; mi < 2; mi++)
#pragma unroll
                for (int np = 0; np < 4; np++) {
                    mma_f16(acc[mi][np * 2],     afr[mi], bfr[np]);
                    mma_f16(acc[mi][np * 2 + 1], afr[mi], bfr[np] + 2);
                }
        }
        __syncthreads();
        if (nx) {
            storeA(a, b);
            stageB(k0 + 64);
            CPA_WAIT0;
            __syncthreads();
        }
    }

    // epilogue: +b2, gelu, fp16-store
#pragma unroll
    for (int mi = 0; mi < 2; mi++) {
        int r0 = e0 + wm + mi * 16 + lr;
#pragma unroll
        for (int ni = 0; ni < 8; ni++) {
            int col = wn + ni * 8 + lc * 2;
            float bb0 = b2[col], bb1 = b2[col + 1];
            *(uint32_t*)(g_H2h + (size_t)r0 * 256 + col) =
                pack_h2(gelu_f(acc[mi][ni][0] + bb0), gelu_f(acc[mi][ni][1] + bb1));
            *(uint32_t*)(g_H2h + (size_t)(r0 + 8) * 256 + col) =
                pack_h2(gelu_f(acc[mi][ni][2] + bb0), gelu_f(acc[mi][ni][3] + bb1));
        }
    }
}

// ---------------------------------------------------------------------------
// GEMM3 + segsum: out = segsum( (H2 @ W3 + b3) * f_y[nbr] )
// BM=128, BN=64, K=256, BK=64. 256 threads = 8 m-warps (m16 x n64).
// ---------------------------------------------------------------------------
__global__ void __launch_bounds__(256) gemm3_mma_kernel(
    const int*   __restrict__ nbr,
    const float* __restrict__ b3,
    const float* __restrict__ fy,
    float*       __restrict__ out)
{
    __shared__ __align__(128) char sA[128 * 128];   // 16 KB
    __shared__ __align__(128) char sB3[64 * 128];   //  8 KB
    __shared__ int s_nbr[128];

    const int tid  = threadIdx.x;
    const int e0   = blockIdx.x * 128;
    const int warp = tid >> 5, lane = tid & 31;
    const int lr = lane >> 2, lc = lane & 3;
    const uint32_t sAu = smem_u32(sA), sBu = smem_u32(sB3);

    if (tid < 128) s_nbr[tid] = nbr[e0 + tid];

    const int ar = tid >> 1, cw = (tid & 1) * 32;   // A: 32 halves/thread
    const __half* pA = g_H2h + (size_t)(e0 + ar) * 256 + cw;
    const int b3n = tid >> 2, b3w = (tid & 3) * 16; // B: 16 halves/thread

    auto stageB = [&](int k0) {
        cpa16(sBu + swb(b3n, b3w),     g_W3T + (size_t)b3n * 256 + k0 + b3w);
        cpa16(sBu + swb(b3n, b3w + 8), g_W3T + (size_t)b3n * 256 + k0 + b3w + 8);
        CPA_COMMIT;
    };
    auto storeA = [&](const uint4* v) {
#pragma unroll
        for (int j = 0; j < 4; j++)
            *(uint4*)(sA + swb(ar, cw + j * 8)) = v[j];
    };

    float acc3[8][4];
#pragma unroll
    for (int ni = 0; ni < 8; ni++)
#pragma unroll
        for (int t = 0; t < 4; t++) acc3[ni][t] = 0.f;

    {   // prologue
        stageB(0);
        uint4 v[4];
#pragma unroll
        for (int j = 0; j < 4; j++) v[j] = *(const uint4*)(pA + j * 8);
        storeA(v);
        CPA_WAIT0;
    }
    __syncthreads();

    for (int k0 = 0; k0 < 256; k0 += 64) {
        const bool nx = (k0 + 64) < 256;
        uint4 v[4];
        if (nx) {
#pragma unroll
            for (int j = 0; j < 4; j++) v[j] = *(const uint4*)(pA + k0 + 64 + j * 8);
        }
#pragma unroll
        for (int kk = 0; kk < 64; kk += 16) {
            uint32_t afr[4], bfr[4][4];
            ldsm_x4(afr, ldsmA_addr(sAu, warp * 16, kk, lane));
#pragma unroll
            for (int np = 0; np < 4; np++)
                ldsm_x4(bfr[np], ldsmB_addr(sBu, np * 16, kk, lane));
#pragma unroll
            for (int np = 0; np < 4; np++) {
                mma_f16(acc3[np * 2],     afr, bfr[np]);
                mma_f16(acc3[np * 2 + 1], afr, bfr[np] + 2);
            }
        }
        __syncthreads();
        if (nx) {
            storeA(v);
            stageB(k0 + 64);
            CPA_WAIT0;
            __syncthreads();
        }
    }

    // epilogue: +b3, *f_y, 16-edge segsum via shuffles (query == m16 tile)
    {
        int r0 = warp * 16 + lr;
        int nb0 = s_nbr[r0], nb1 = s_nbr[r0 + 8];
        const int q = blockIdx.x * 8 + warp;
#pragma unroll
        for (int ni = 0; ni < 8; ni++) {
            int col = ni * 8 + lc * 2;
            float bb0 = b3[col], bb1 = b3[col + 1];
            float2 f0 = *(const float2*)(fy + (size_t)nb0 * 64 + col);
            float2 f1 = *(const float2*)(fy + (size_t)nb1 * 64 + col);
            float s0 = (acc3[ni][0] + bb0) * f0.x + (acc3[ni][2] + bb0) * f1.x;
            float s1 = (acc3[ni][1] + bb1) * f0.y + (acc3[ni][3] + bb1) * f1.y;
#pragma unroll
            for (int off = 4; off <= 16; off <<= 1) {
                s0 += __shfl_xor_sync(0xFFFFFFFFu, s0, off);
                s1 += __shfl_xor_sync(0xFFFFFFFFu, s1, off);
            }
            if (lr == 0)
                *(float2*)(out + (size_t)q * 64 + col) = make_float2(s0, s1);
        }
    }
}

// ---------------------------------------------------------------------------
extern "C" void kernel_launch(void* const* d_in, const int* in_sizes, int n_in,
                              void* d_out, int out_size)
{
    const float* y   = (const float*)d_in[0];
    const float* x   = (const float*)d_in[1];
    const float* f_y = (const float*)d_in[2];
    const int*   nbr = (const int*)d_in[3];
    // d_in[4] = neighbors_row_splits (uniform K=16 -> q = e>>4)
    const float* W1  = (const float*)d_in[5];
    const float* b1  = (const float*)d_in[6];
    const float* W2  = (const float*)d_in[7];
    const float* b2  = (const float*)d_in[8];
    const float* W3  = (const float*)d_in[9];
    const float* b3  = (const float*)d_in[10];
    float* out = (float*)d_out;

    dim3 tb(32, 8);
    transpose_cvt_kernel<<<dim3(8, 6), tb>>>(W1,             192, 256, 0);
    transpose_cvt_kernel<<<dim3(8, 6), tb>>>(W1 + 192 * 256, 192, 256, 1);
    transpose_cvt_kernel<<<dim3(8, 8), tb>>>(W2,             256, 256, 2);
    transpose_cvt_kernel<<<dim3(2, 8), tb>>>(W3,             256,  64, 3);

    embed_mma_kernel<<<(N_Y + 127) / 128, 512>>>(y, nullptr, 0, N_Y);
    embed_mma_kernel<<<(N_X + 127) / 128, 512>>>(x, b1, 1, N_X);
    gemm2_mma_kernel<<<NE / 128, 512>>>(nbr, b2);
    gemm3_mma_kernel<<<NE / 128, 256>>>(nbr, b3, f_y, out);
}

// round 8
// speedup vs baseline: 1.9457x; 1.0628x over previous
#include <cuda_runtime.h>
#include <cuda_fp16.h>
#include <math.h>
#include <stdint.h>

#define N_Y   100000
#define N_X   20000
#define KNN   16
#define NE    (N_X * KNN)      // 320000 edges
#define HID   256
#define CIN   64

// Scratch (device globals: allocation-free contract)
__device__ __half  g_Ayh[(size_t)N_Y * HID];   // 51.2 MB (L2-resident)
__device__ __half  g_Bxh[(size_t)N_X * HID];   // 10.2 MB
__device__ __half  g_H2h[(size_t)NE * HID];
// transposed + fp16-converted weights, [n][k] dense
__device__ __half  g_W1aT[256 * 192];
__device__ __half  g_W1bT[256 * 192];
__device__ __half  g_W2T[256 * 256];
__device__ __half  g_W3T[64 * 256];

__device__ __forceinline__ float gelu_f(float v) {
    return 0.5f * v * (1.0f + erff(v * 0.70710678118654752f));
}
__device__ __forceinline__ uint32_t pack_h2(float lo, float hi) {
    __half2 h = __floats2half2_rn(lo, hi);
    return *reinterpret_cast<uint32_t*>(&h);
}
__device__ __forceinline__ void mma_f16(float* d, const uint32_t* a, const uint32_t* b) {
    asm volatile(
        "mma.sync.aligned.m16n8k16.row.col.f32.f16.f16.f32 "
        "{%0,%1,%2,%3}, {%4,%5,%6,%7}, {%8,%9}, {%0,%1,%2,%3};\n"
        : "+f"(d[0]), "+f"(d[1]), "+f"(d[2]), "+f"(d[3])
        : "r"(a[0]), "r"(a[1]), "r"(a[2]), "r"(a[3]), "r"(b[0]), "r"(b[1]));
}
__device__ __forceinline__ void ldsm_x4(uint32_t* r, uint32_t saddr) {
    asm volatile("ldmatrix.sync.aligned.m8n8.x4.shared.b16 {%0,%1,%2,%3}, [%4];"
                 : "=r"(r[0]), "=r"(r[1]), "=r"(r[2]), "=r"(r[3]) : "r"(saddr));
}
__device__ __forceinline__ uint32_t smem_u32(const void* p) {
    return (uint32_t)__cvta_generic_to_shared(p);
}
__device__ __forceinline__ void cpa16(uint32_t dst, const void* src) {
    asm volatile("cp.async.ca.shared.global [%0], [%1], 16;\n" :: "r"(dst), "l"(src));
}
#define CPA_COMMIT asm volatile("cp.async.commit_group;\n")
#define CPA_WAIT0  asm volatile("cp.async.wait_group 0;\n")

// BK=32 fp16 tile: row = 32 halves = 64 B = 4 chunks of 16 B.
// swizzle: chunk' = chunk ^ ((r>>1)&3)  -> 8-row ldmatrix phases conflict-free.
__device__ __forceinline__ uint32_t swb32(int r, int chalf) {   // chalf mult of 8
    return (uint32_t)(r * 64) + (uint32_t)((((chalf >> 3) ^ ((r >> 1) & 3)) << 4));
}
__device__ __forceinline__ uint32_t ldsmA32(uint32_t base, int m0, int kk, int lane) {
    int r = m0 + (lane & 15);
    int ch = (kk >> 3) + (lane >> 4);
    return base + (uint32_t)(r * 64) + (uint32_t)(((ch ^ ((r >> 1) & 3)) << 4));
}
__device__ __forceinline__ uint32_t ldsmB32(uint32_t base, int n0, int kk, int lane) {
    int r = n0 + (lane & 7) + ((lane >> 4) << 3);
    int ch = (kk >> 3) + ((lane >> 3) & 1);
    return base + (uint32_t)(r * 64) + (uint32_t)(((ch ^ ((r >> 1) & 3)) << 4));
}

// ---------------------------------------------------------------------------
// One-launch weight transpose + fp16 convert for all 4 matrices.
// fp32 [K][N] -> half [N][K]. 32x32 tiles; 176 blocks total.
// ---------------------------------------------------------------------------
__global__ void transpose_all_kernel(const float* __restrict__ W1,
                                     const float* __restrict__ W2,
                                     const float* __restrict__ W3)
{
    __shared__ float t[32][33];
    int id = blockIdx.x;
    const float* src; __half* dst; int K, N, local;
    if (id < 48)       { src = W1;             dst = g_W1aT; K = 192; N = 256; local = id; }
    else if (id < 96)  { src = W1 + 192 * 256; dst = g_W1bT; K = 192; N = 256; local = id - 48; }
    else if (id < 160) { src = W2;             dst = g_W2T;  K = 256; N = 256; local = id - 96; }
    else               { src = W3;             dst = g_W3T;  K = 256; N = 64;  local = id - 160; }
    int nbx = N / 32;
    int n0 = (local % nbx) * 32, k0 = (local / nbx) * 32;
    int tx = threadIdx.x, ty = threadIdx.y;   // 32 x 8
#pragma unroll
    for (int i = 0; i < 32; i += 8)
        t[ty + i][tx] = src[(size_t)(k0 + ty + i) * N + n0 + tx];
    __syncthreads();
#pragma unroll
    for (int i = 0; i < 32; i += 8)
        dst[(size_t)(n0 + ty + i) * K + k0 + tx] = __float2half(t[tx][ty + i]);
}

// ---------------------------------------------------------------------------
// Embed + GEMM1: dst = emb(pts) @ W (+bias).  BM=128, BN=256, K=192, BK=32,
// 2-stage double buffer.  512 threads = 16 warps (4m x 4n), warp 32x64.
// ---------------------------------------------------------------------------
__global__ void __launch_bounds__(512) embed_mma_kernel(
    const float* __restrict__ pts,
    const float* __restrict__ bias,
    int which, int n)
{
    __shared__ __align__(128) char sA[2 * 128 * 64];   // 16 KB
    __shared__ __align__(128) char sB[2 * 256 * 64];   // 32 KB

    const __half* WT = which ? g_W1bT : g_W1aT;
    __half* dst = which ? g_Bxh : g_Ayh;
    const int tid  = threadIdx.x;
    const int row0 = blockIdx.x * 128;
    const int warp = tid >> 5, lane = tid & 31;
    const int wm = (warp & 3) * 32, wn = (warp >> 2) * 64;
    const int lr = lane >> 2, lc = lane & 3;
    const uint32_t sAu = smem_u32(sA), sBu = smem_u32(sB);

    const int ar = tid >> 2, cb = (tid & 3) * 8;   // A: 8 halves/thread
    const int arow = row0 + ar;
    float3 p = make_float3(0.f, 0.f, 0.f);
    if (arow < n) { p.x = pts[arow * 3]; p.y = pts[arow * 3 + 1]; p.z = pts[arow * 3 + 2]; }
    const int bn = tid >> 1, bw = (tid & 1) * 16;  // B: 16 halves/thread

    auto storeA = [&](int pbuf, int k0) {   // compute 4 sincos pairs + STS
        int e0e = k0 + cb;
        int c = e0e >> 6;
        float pc = c == 0 ? p.x : (c == 1 ? p.y : p.z);
        int fb = (e0e & 63) >> 1;
        uint32_t w[4];
#pragma unroll
        for (int i = 0; i < 4; i++) {
            float freq = exp2f(-0.41524101186f * (float)(fb + i));
            float s, cf;
            sincosf(pc * freq, &s, &cf);
            w[i] = pack_h2(s, cf);
        }
        *(uint4*)(sA + pbuf * 8192 + swb32(ar, cb)) = make_uint4(w[0], w[1], w[2], w[3]);
    };
    auto stageB = [&](int k0, int pbuf) {
        char* base = sB + pbuf * 16384;
        cpa16(smem_u32(base + swb32(bn, bw)),     WT + (size_t)bn * 192 + k0 + bw);
        cpa16(smem_u32(base + swb32(bn, bw + 8)), WT + (size_t)bn * 192 + k0 + bw + 8);
        CPA_COMMIT;
    };

    float acc[2][8][4];
#pragma unroll
    for (int mi = 0; mi < 2; mi++)
#pragma unroll
        for (int ni = 0; ni < 8; ni++)
#pragma unroll
            for (int t = 0; t < 4; t++) acc[mi][ni][t] = 0.f;

    storeA(0, 0);
    stageB(0, 0);

    const int NCH = 6;   // 192/32
    for (int i = 0; i < NCH; i++) {
        const int pb = i & 1;
        CPA_WAIT0;
        __syncthreads();
        if (i + 1 < NCH) stageB((i + 1) * 32, 1 - pb);
        const uint32_t aBase = sAu + pb * 8192, bBase = sBu + pb * 16384;
#pragma unroll
        for (int kk = 0; kk < 32; kk += 16) {
            uint32_t afr[2][4], bfr[4][4];
#pragma unroll
            for (int mi = 0; mi < 2; mi++)
                ldsm_x4(afr[mi], ldsmA32(aBase, wm + mi * 16, kk, lane));
#pragma unroll
            for (int np = 0; np < 4; np++)
                ldsm_x4(bfr[np], ldsmB32(bBase, wn + np * 16, kk, lane));
#pragma unroll
            for (int mi = 0; mi < 2; mi++)
#pragma unroll
                for (int np = 0; np < 4; np++) {
                    mma_f16(acc[mi][np * 2],     afr[mi], bfr[np]);
                    mma_f16(acc[mi][np * 2 + 1], afr[mi], bfr[np] + 2);
                }
        }
        if (i + 1 < NCH) storeA(1 - pb, (i + 1) * 32);
    }

    // epilogue: +bias, fp16 store (guarded)
#pragma unroll
    for (int mi = 0; mi < 2; mi++) {
        int r0 = row0 + wm + mi * 16 + lr;
        int r1 = r0 + 8;
#pragma unroll
        for (int ni = 0; ni < 8; ni++) {
            int col = wn + ni * 8 + lc * 2;
            float bb0 = bias ? bias[col]     : 0.f;
            float bb1 = bias ? bias[col + 1] : 0.f;
            if (r0 < n)
                *(uint32_t*)(dst + (size_t)r0 * 256 + col) =
                    pack_h2(acc[mi][ni][0] + bb0, acc[mi][ni][1] + bb1);
            if (r1 < n)
                *(uint32_t*)(dst + (size_t)r1 * 256 + col) =
                    pack_h2(acc[mi][ni][2] + bb0, acc[mi][ni][3] + bb1);
        }
    }
}

// ---------------------------------------------------------------------------
// GEMM2 (fused gather+gelu): H2h = h(gelu( gelu(Ayh[nbr]+Bxh[q]) @ W2 + b2 ))
// BM=128, BN=256, K=256, BK=32, 2-stage. 512 threads.
// ---------------------------------------------------------------------------
__global__ void __launch_bounds__(512) gemm2_mma_kernel(
    const int*   __restrict__ nbr,
    const float* __restrict__ b2)
{
    __shared__ __align__(128) char sA[2 * 128 * 64];
    __shared__ __align__(128) char sB[2 * 256 * 64];

    const int tid  = threadIdx.x;
    const int e0   = blockIdx.x * 128;
    const int warp = tid >> 5, lane = tid & 31;
    const int wm = (warp & 3) * 32, wn = (warp >> 2) * 64;
    const int lr = lane >> 2, lc = lane & 3;
    const uint32_t sAu = smem_u32(sA), sBu = smem_u32(sB);

    const int ar = tid >> 2, cb = (tid & 3) * 8;
    const int nb = nbr[e0 + ar];
    const __half* pA = g_Ayh + (size_t)nb * 256 + cb;
    const __half* pB = g_Bxh + (size_t)((e0 + ar) >> 4) * 256 + cb;
    const int bn = tid >> 1, bw = (tid & 1) * 16;

    auto stageB = [&](int k0, int pbuf) {
        char* base = sB + pbuf * 16384;
        cpa16(smem_u32(base + swb32(bn, bw)),     g_W2T + (size_t)bn * 256 + k0 + bw);
        cpa16(smem_u32(base + swb32(bn, bw + 8)), g_W2T + (size_t)bn * 256 + k0 + bw + 8);
        CPA_COMMIT;
    };
    auto storeA = [&](int pbuf, uint4 aq, uint4 bq) {
        const __half2* ah = (const __half2*)&aq;
        const __half2* bh = (const __half2*)&bq;
        uint32_t w[4];
#pragma unroll
        for (int j = 0; j < 4; j++) {
            float2 af = __half22float2(ah[j]);
            float2 bf = __half22float2(bh[j]);
            w[j] = pack_h2(gelu_f(af.x + bf.x), gelu_f(af.y + bf.y));
        }
        *(uint4*)(sA + pbuf * 8192 + swb32(ar, cb)) = make_uint4(w[0], w[1], w[2], w[3]);
    };

    float acc[2][8][4];
#pragma unroll
    for (int mi = 0; mi < 2; mi++)
#pragma unroll
        for (int ni = 0; ni < 8; ni++)
#pragma unroll
            for (int t = 0; t < 4; t++) acc[mi][ni][t] = 0.f;

    {   // prologue: chunk 0 into buf 0
        uint4 aq = *(const uint4*)(pA);
        uint4 bq = *(const uint4*)(pB);
        storeA(0, aq, bq);
        stageB(0, 0);
    }

    const int NCH = 8;   // 256/32
    for (int i = 0; i < NCH; i++) {
        const int pb = i & 1;
        CPA_WAIT0;
        __syncthreads();
        uint4 aq, bq;
        if (i + 1 < NCH) {
            aq = *(const uint4*)(pA + (i + 1) * 32);
            bq = *(const uint4*)(pB + (i + 1) * 32);
            stageB((i + 1) * 32, 1 - pb);
        }
        const uint32_t aBase = sAu + pb * 8192, bBase = sBu + pb * 16384;
#pragma unroll
        for (int kk = 0; kk < 32; kk += 16) {
            uint32_t afr[2][4], bfr[4][4];
#pragma unroll
            for (int mi = 0; mi < 2; mi++)
                ldsm_x4(afr[mi], ldsmA32(aBase, wm + mi * 16, kk, lane));
#pragma unroll
            for (int np = 0; np < 4; np++)
                ldsm_x4(bfr[np], ldsmB32(bBase, wn + np * 16, kk, lane));
#pragma unroll
            for (int mi = 0; mi < 2; mi++)
#pragma unroll
                for (int np = 0; np < 4; np++) {
                    mma_f16(acc[mi][np * 2],     afr[mi], bfr[np]);
                    mma_f16(acc[mi][np * 2 + 1], afr[mi], bfr[np] + 2);
                }
        }
        if (i + 1 < NCH) storeA(1 - pb, aq, bq);
    }

    // epilogue: +b2, gelu, fp16-store
#pragma unroll
    for (int mi = 0; mi < 2; mi++) {
        int r0 = e0 + wm + mi * 16 + lr;
#pragma unroll
        for (int ni = 0; ni < 8; ni++) {
            int col = wn + ni * 8 + lc * 2;
            float bb0 = b2[col], bb1 = b2[col + 1];
            *(uint32_t*)(g_H2h + (size_t)r0 * 256 + col) =
                pack_h2(gelu_f(acc[mi][ni][0] + bb0), gelu_f(acc[mi][ni][1] + bb1));
            *(uint32_t*)(g_H2h + (size_t)(r0 + 8) * 256 + col) =
                pack_h2(gelu_f(acc[mi][ni][2] + bb0), gelu_f(acc[mi][ni][3] + bb1));
        }
    }
}

// ---------------------------------------------------------------------------
// GEMM3 + segsum: out = segsum( (H2 @ W3 + b3) * f_y[nbr] )
// BM=128, BN=64, K=256, BK=32, 2-stage, all-cp.async staging.
// 256 threads = 8 m-warps (m16 x n64). Query == m16 tile.
// ---------------------------------------------------------------------------
__global__ void __launch_bounds__(256) gemm3_mma_kernel(
    const int*   __restrict__ nbr,
    const float* __restrict__ b3,
    const float* __restrict__ fy,
    float*       __restrict__ out)
{
    __shared__ __align__(128) char sA[2 * 128 * 64];   // 16 KB
    __shared__ __align__(128) char sB3[2 * 64 * 64];   //  8 KB
    __shared__ int s_nbr[128];

    const int tid  = threadIdx.x;
    const int e0   = blockIdx.x * 128;
    const int warp = tid >> 5, lane = tid & 31;
    const int lr = lane >> 2, lc = lane & 3;
    const uint32_t sAu = smem_u32(sA), sBu = smem_u32(sB3);

    if (tid < 128) s_nbr[tid] = nbr[e0 + tid];

    const int ar = tid >> 1, cw = (tid & 1) * 16;   // A: 16 halves/thread (2 chunks)
    const __half* pA = g_H2h + (size_t)(e0 + ar) * 256 + cw;
    const int b3n = tid >> 2, b3w = (tid & 3) * 8;  // B: 8 halves/thread (1 chunk)

    auto stage = [&](int k0, int pbuf) {
        char* abase = sA + pbuf * 8192;
        cpa16(smem_u32(abase + swb32(ar, cw)),     pA + k0);
        cpa16(smem_u32(abase + swb32(ar, cw + 8)), pA + k0 + 8);
        cpa16(smem_u32(sB3 + pbuf * 4096 + swb32(b3n, b3w)),
              g_W3T + (size_t)b3n * 256 + k0 + b3w);
        CPA_COMMIT;
    };

    float acc3[8][4];
#pragma unroll
    for (int ni = 0; ni < 8; ni++)
#pragma unroll
        for (int t = 0; t < 4; t++) acc3[ni][t] = 0.f;

    stage(0, 0);

    const int NCH = 8;
    for (int i = 0; i < NCH; i++) {
        const int pb = i & 1;
        CPA_WAIT0;
        __syncthreads();
        if (i + 1 < NCH) stage((i + 1) * 32, 1 - pb);
        const uint32_t aBase = sAu + pb * 8192, bBase = sBu + pb * 4096;
#pragma unroll
        for (int kk = 0; kk < 32; kk += 16) {
            uint32_t afr[4], bfr[4][4];
            ldsm_x4(afr, ldsmA32(aBase, warp * 16, kk, lane));
#pragma unroll
            for (int np = 0; np < 4; np++)
                ldsm_x4(bfr[np], ldsmB32(bBase, np * 16, kk, lane));
#pragma unroll
            for (int np = 0; np < 4; np++) {
                mma_f16(acc3[np * 2],     afr, bfr[np]);
                mma_f16(acc3[np * 2 + 1], afr, bfr[np] + 2);
            }
        }
    }

    // epilogue: +b3, *f_y, 16-edge segsum via shuffles (query == m16 tile)
    {
        int r0 = warp * 16 + lr;
        int nb0 = s_nbr[r0], nb1 = s_nbr[r0 + 8];
        const int q = blockIdx.x * 8 + warp;
#pragma unroll
        for (int ni = 0; ni < 8; ni++) {
            int col = ni * 8 + lc * 2;
            float bb0 = b3[col], bb1 = b3[col + 1];
            float2 f0 = *(const float2*)(fy + (size_t)nb0 * 64 + col);
            float2 f1 = *(const float2*)(fy + (size_t)nb1 * 64 + col);
            float s0 = (acc3[ni][0] + bb0) * f0.x + (acc3[ni][2] + bb0) * f1.x;
            float s1 = (acc3[ni][1] + bb1) * f0.y + (acc3[ni][3] + bb1) * f1.y;
#pragma unroll
            for (int off = 4; off <= 16; off <<= 1) {
                s0 += __shfl_xor_sync(0xFFFFFFFFu, s0, off);
                s1 += __shfl_xor_sync(0xFFFFFFFFu, s1, off);
            }
            if (lr == 0)
                *(float2*)(out + (size_t)q * 64 + col) = make_float2(s0, s1);
        }
    }
}

// ---------------------------------------------------------------------------
extern "C" void kernel_launch(void* const* d_in, const int* in_sizes, int n_in,
                              void* d_out, int out_size)
{
    const float* y   = (const float*)d_in[0];
    const float* x   = (const float*)d_in[1];
    const float* f_y = (const float*)d_in[2];
    const int*   nbr = (const int*)d_in[3];
    // d_in[4] = neighbors_row_splits (uniform K=16 -> q = e>>4)
    const float* W1  = (const float*)d_in[5];
    const float* b1  = (const float*)d_in[6];
    const float* W2  = (const float*)d_in[7];
    const float* b2  = (const float*)d_in[8];
    const float* W3  = (const float*)d_in[9];
    const float* b3  = (const float*)d_in[10];
    float* out = (float*)d_out;

    transpose_all_kernel<<<176, dim3(32, 8)>>>(W1, W2, W3);
    embed_mma_kernel<<<(N_Y + 127) / 128, 512>>>(y, nullptr, 0, N_Y);
    embed_mma_kernel<<<(N_X + 127) / 128, 512>>>(x, b1, 1, N_X);
    gemm2_mma_kernel<<<NE / 128, 512>>>(nbr, b2);
    gemm3_mma_kernel<<<NE / 128, 256>>>(nbr, b3, f_y, out);
}